// round 5
// baseline (speedup 1.0000x reference)
#include <cuda_runtime.h>

#define LFRAMES 120000
#define C       256
#define TL      64
#define NTH     256
#define TSAMP   600000
#define HSTRIDE 68

__device__ float g_bufA[LFRAMES * C];   // res ping
__device__ float g_bufB[LFRAMES * C];   // res pong
__device__ float g_bufC[LFRAMES * C];   // ci stream (blocks 1,3)
__device__ float g_bufD[LFRAMES * C];   // ci stream (block 2)

typedef unsigned long long u64;

__device__ __forceinline__ float leakyf(float x) { return x >= 0.0f ? x : 0.3f * x; }

// exact-division quantize (reference-matching); used only in cold paths
__device__ __forceinline__ float quant_div(float x, float s, float o) {
    float q = rintf(x / s - o);
    return fminf(fmaxf(q, -128.0f), 127.0f);
}
// reciprocal-multiply quantize; only for continuous-valued inputs
__device__ __forceinline__ float quant_mul(float x, float is, float o) {
    float q = rintf(x * is - o);
    return fminf(fmaxf(q, -128.0f), 127.0f);
}

__device__ __forceinline__ u64 pk2(float lo, float hi) {
    u64 r; asm("mov.b64 %0, {%1, %2};" : "=l"(r) : "f"(lo), "f"(hi)); return r;
}
__device__ __forceinline__ u64 ffma2(u64 a, u64 b, u64 c) {
    u64 d; asm("fma.rn.f32x2 %0, %1, %2, %3;" : "=l"(d) : "l"(a), "l"(b), "l"(c)); return d;
}
__device__ __forceinline__ float2 up2(u64 v) {
    float2 r; asm("mov.b64 {%0, %1}, %2;" : "=f"(r.x), "=f"(r.y) : "l"(v)); return r;
}

// -------------------------------------------------------------------------
// Kernel 1: first conv (k=10, stride=5, 1->256) + bias; also emits ci1=leaky
// -------------------------------------------------------------------------
__global__ __launch_bounds__(NTH) void k_first(
    const float* __restrict__ x, const float* __restrict__ fb,
    const float* __restrict__ wf, const float* __restrict__ bf,
    float* __restrict__ res, float* __restrict__ ci)
{
    __shared__ float sx[5 * TL + 10];
    const int l0  = blockIdx.x * TL;
    const int tid = threadIdx.x;
    const int base = 5 * l0;

    for (int i = tid; i < 5 * TL + 10; i += NTH) {
        int t = base + i;
        float v;
        if (t < 5)                 v = fb[t];
        else if (t - 5 < TSAMP)    v = x[t - 5];
        else                       v = 0.0f;
        sx[i] = v;
    }

    float w[10];
#pragma unroll
    for (int k = 0; k < 10; k++) w[k] = wf[k * C + tid];
    const float b = bf[tid];
    __syncthreads();

    for (int f = 0; f < TL; f++) {
        float acc = b;
#pragma unroll
        for (int k = 0; k < 10; k++) acc = fmaf(sx[5 * f + k], w[k], acc);
        res[(l0 + f) * C + tid] = acc;
        ci[(l0 + f) * C + tid]  = leakyf(acc);
    }
}

// -------------------------------------------------------------------------
// 256-deep GEMM, packed f32x2 FMAs, transposed input operand in sB.
// -------------------------------------------------------------------------
__device__ __forceinline__ void gemm256t(
    u64 acc[8][4], const float* __restrict__ sIn, float* sW,
    const float* __restrict__ Wg, int ty, int tx, int tid)
{
    for (int kb = 0; kb < 8; kb++) {
        __syncthreads();
        const float4* wg  = (const float4*)(Wg + kb * 32 * C);
        float4*       sw4 = (float4*)sW;
#pragma unroll
        for (int i = 0; i < 8; i++) sw4[tid + i * NTH] = wg[tid + i * NTH];
        __syncthreads();

#pragma unroll 4
        for (int kk = 0; kk < 32; kk++) {
            const int k = kb * 32 + kk;
            const float4* hp = (const float4*)(sIn + k * HSTRIDE + ty * 8);
            float4 ha = hp[0], hb = hp[1];
            u64 hh[8];
            hh[0] = pk2(ha.x, ha.x); hh[1] = pk2(ha.y, ha.y);
            hh[2] = pk2(ha.z, ha.z); hh[3] = pk2(ha.w, ha.w);
            hh[4] = pk2(hb.x, hb.x); hh[5] = pk2(hb.y, hb.y);
            hh[6] = pk2(hb.z, hb.z); hh[7] = pk2(hb.w, hb.w);
            const u64* wA = (const u64*)(sW + kk * C + tx * 4);
            const u64* wB = (const u64*)(sW + kk * C + 128 + tx * 4);
            u64 ww0 = wA[0], ww1 = wA[1], ww2 = wB[0], ww3 = wB[1];
#pragma unroll
            for (int i = 0; i < 8; i++) {
                acc[i][0] = ffma2(hh[i], ww0, acc[i][0]);
                acc[i][1] = ffma2(hh[i], ww1, acc[i][1]);
                acc[i][2] = ffma2(hh[i], ww2, acc[i][2]);
                acc[i][3] = ffma2(hh[i], ww3, acc[i][3]);
            }
        }
    }
}

// -------------------------------------------------------------------------
// Fused residual block. ci is read from a precomputed global stream.
// smem layout: [LUT 256][sW 32*256][sB C*HSTRIDE]  ~103KB -> 2 CTAs/SM
// -------------------------------------------------------------------------
template <int MODE, int DIL>
__global__ __launch_bounds__(NTH, 2) void k_block(
    const float* __restrict__ src,  const float* __restrict__ ciG,
    const float* __restrict__ cbuf,
    const float* __restrict__ wdw,  const float* __restrict__ bdw,
    const float* __restrict__ wpw,  const float* __restrict__ bpw,
    const float* __restrict__ wlc,  const float* __restrict__ blc,
    float* __restrict__ dst,        float* __restrict__ ciOut)
{
    constexpr int PAD = 2 * DIL;
    constexpr float S2 = 5.548006534576416f;
    constexpr float S3 = 4.458680152893066f;
    constexpr float INV_Q1  = (float)(1.0 / 17.62967872619629);
    constexpr float INV_RQ1 = (float)(1.0 / 12.716455459594727);
    constexpr float INV_S3  = (float)(1.0 / 4.458680152893066);

    extern __shared__ float sm[];
    float* sLUT = sm;              // 256
    float* sW   = sm + 256;        // 32*C
    float* sB   = sm + 256 + 32 * C;  // C*HSTRIDE

    const int l0  = blockIdx.x * TL;
    const int tid = threadIdx.x;
    const int ty  = tid >> 5;
    const int tx  = tid & 31;

    // LUT for MODE1's ci2 emission: n -> quant(dequant(leaky(n))) exact
    if (MODE == 1) {
        float n = (float)(tid - 128);
        float v = leakyf(n);
        float d = (v + 47.0f) * S2;
        sLUT[tid] = quant_div(d, S2, 47.0f);
    }

    // 1) depthwise conv (k=3, dilation DIL) from global ci stream -> H^T
    {
        const float w0 = wdw[tid], w1 = wdw[C + tid], w2 = wdw[2 * C + tid];
        const float bb = bdw[tid];
        for (int r = 0; r < TL; r++) {
            const int t0 = l0 + r - 2 * DIL;
            const int t1 = l0 + r - DIL;
            float c0, c1;
            if (t0 >= 0) c0 = ciG[t0 * C + tid];
            else {
                float bv = cbuf[(t0 + PAD) * C + tid];
                c0 = (MODE == 1) ? bv : (MODE == 2 ? quant_div(bv, S2, 47.0f)
                                                   : quant_div(bv, S3, 38.0f));
            }
            if (t1 >= 0) c1 = ciG[t1 * C + tid];
            else {
                float bv = cbuf[(t1 + PAD) * C + tid];
                c1 = (MODE == 1) ? bv : (MODE == 2 ? quant_div(bv, S2, 47.0f)
                                                   : quant_div(bv, S3, 38.0f));
            }
            float c2 = ciG[(l0 + r) * C + tid];
            float h = bb;
            h = fmaf(c0, w0, h);
            h = fmaf(c1, w1, h);
            h = fmaf(c2, w2, h);
            sB[tid * HSTRIDE + r] = h;
        }
    }
    __syncthreads();

    // 2) GEMM1: P = H @ Wpw + bpw
    u64 acc[8][4];
    {
        const u64* bA = (const u64*)(bpw + tx * 4);
        const u64* bB = (const u64*)(bpw + 128 + tx * 4);
        u64 b0 = bA[0], b1 = bA[1], b2 = bB[0], b3 = bB[1];
#pragma unroll
        for (int i = 0; i < 8; i++) {
            acc[i][0] = b0; acc[i][1] = b1; acc[i][2] = b2; acc[i][3] = b3;
        }
    }
    gemm256t(acc, sB, sW, wpw, ty, tx, tid);
    __syncthreads();

    // 2b) epilogue: activation, store P transposed
#pragma unroll
    for (int jj = 0; jj < 4; jj++) {
        const int cbase = (jj < 2) ? (tx * 4 + 2 * jj) : (128 + tx * 4 + 2 * (jj - 2));
        float2 v[8];
#pragma unroll
        for (int i = 0; i < 8; i++) {
            float2 p = up2(acc[i][jj]);
            if (MODE == 1) {
                p.x = quant_mul(p.x, INV_Q1, -67.0f);   // continuous input: recip OK
                p.y = quant_mul(p.y, INV_Q1, -67.0f);
            }
            p.x = leakyf(p.x); p.y = leakyf(p.y);
            v[i] = p;
        }
        float4* d0 = (float4*)(sB + cbase * HSTRIDE + ty * 8);
        float4* d1 = (float4*)(sB + (cbase + 1) * HSTRIDE + ty * 8);
        d0[0] = make_float4(v[0].x, v[1].x, v[2].x, v[3].x);
        d0[1] = make_float4(v[4].x, v[5].x, v[6].x, v[7].x);
        d1[0] = make_float4(v[0].y, v[1].y, v[2].y, v[3].y);
        d1[1] = make_float4(v[4].y, v[5].y, v[6].y, v[7].y);
    }
    __syncthreads();

    // 3) GEMM2: O = P @ Wlc + blc
    {
        const u64* bA = (const u64*)(blc + tx * 4);
        const u64* bB = (const u64*)(blc + 128 + tx * 4);
        u64 b0 = bA[0], b1 = bA[1], b2 = bB[0], b3 = bB[1];
#pragma unroll
        for (int i = 0; i < 8; i++) {
            acc[i][0] = b0; acc[i][1] = b1; acc[i][2] = b2; acc[i][3] = b3;
        }
    }
    gemm256t(acc, sB, sW, wlc, ty, tx, tid);

    // 4) residual + outputs (+ next block's ci stream)
#pragma unroll
    for (int i = 0; i < 8; i++) {
        const int l = l0 + ty * 8 + i;
#pragma unroll
        for (int jj = 0; jj < 4; jj++) {
            const int c = (jj < 2) ? (tx * 4 + 2 * jj) : (128 + tx * 4 + 2 * (jj - 2));
            float2 o = up2(acc[i][jj]);
            float2 r = *((const float2*)(src + l * C + c));
            float2 val, civ;
            if (MODE == 1) {
                float dqx = (o.x - 16.0f) * 6.528060436248779f;
                float dqy = (o.y - 16.0f) * 6.528060436248779f;
                val.x = quant_mul(r.x + dqx, INV_RQ1, -23.0f);  // continuous: recip OK
                val.y = quant_mul(r.y + dqy, INV_RQ1, -23.0f);
                civ.x = sLUT[(int)val.x + 128];                  // discrete: exact LUT
                civ.y = sLUT[(int)val.y + 128];
            } else if (MODE == 2) {
                val.x = o.x + r.x;
                val.y = o.y + r.y;
                float dx = (leakyf(val.x) + 38.0f) * S3;         // continuous: recip OK
                float dy = (leakyf(val.y) + 38.0f) * S3;
                civ.x = quant_mul(dx, INV_S3, 38.0f);
                civ.y = quant_mul(dy, INV_S3, 38.0f);
            } else {
                val.x = (leakyf(o.x + r.x) + 34.0f) * 3.698859930038452f;
                val.y = (leakyf(o.y + r.y) + 34.0f) * 3.698859930038452f;
            }
            *((float2*)(dst + l * C + c)) = val;
            if (MODE != 3) *((float2*)(ciOut + l * C + c)) = civ;
        }
    }
}

// -------------------------------------------------------------------------
extern "C" void kernel_launch(void* const* d_in, const int* in_sizes, int n_in,
                              void* d_out, int out_size)
{
    (void)in_sizes; (void)n_in; (void)out_size;
    const float* x    = (const float*)d_in[0];
    const float* fb   = (const float*)d_in[1];
    const float* r1b  = (const float*)d_in[2];
    const float* r2b  = (const float*)d_in[3];
    const float* r3b  = (const float*)d_in[4];
    const float* wf   = (const float*)d_in[5];
    const float* bf   = (const float*)d_in[6];
    const float* wdw1 = (const float*)d_in[7],  *bdw1 = (const float*)d_in[8];
    const float* wpw1 = (const float*)d_in[9],  *bpw1 = (const float*)d_in[10];
    const float* wlc1 = (const float*)d_in[11], *blc1 = (const float*)d_in[12];
    const float* wdw2 = (const float*)d_in[13], *bdw2 = (const float*)d_in[14];
    const float* wpw2 = (const float*)d_in[15], *bpw2 = (const float*)d_in[16];
    const float* wlc2 = (const float*)d_in[17], *blc2 = (const float*)d_in[18];
    const float* wdw3 = (const float*)d_in[19], *bdw3 = (const float*)d_in[20];
    const float* wpw3 = (const float*)d_in[21], *bpw3 = (const float*)d_in[22];
    const float* wlc3 = (const float*)d_in[23], *blc3 = (const float*)d_in[24];
    float* out = (float*)d_out;

    float *bufA, *bufB, *bufC, *bufD;
    cudaGetSymbolAddress((void**)&bufA, g_bufA);
    cudaGetSymbolAddress((void**)&bufB, g_bufB);
    cudaGetSymbolAddress((void**)&bufC, g_bufC);
    cudaGetSymbolAddress((void**)&bufD, g_bufD);

    const int SMB = (256 + 32 * C + C * HSTRIDE) * 4;  // ~103.4 KB
    cudaFuncSetAttribute(k_block<1, 1>, cudaFuncAttributeMaxDynamicSharedMemorySize, SMB);
    cudaFuncSetAttribute(k_block<2, 3>, cudaFuncAttributeMaxDynamicSharedMemorySize, SMB);
    cudaFuncSetAttribute(k_block<3, 9>, cudaFuncAttributeMaxDynamicSharedMemorySize, SMB);

    const int NBLK = LFRAMES / TL;  // 1875

    k_first<<<NBLK, NTH>>>(x, fb, wf, bf, bufA, bufC);
    k_block<1, 1><<<NBLK, NTH, SMB>>>(bufA, bufC, r1b, wdw1, bdw1, wpw1, bpw1,
                                      wlc1, blc1, bufB, bufD);
    k_block<2, 3><<<NBLK, NTH, SMB>>>(bufB, bufD, r2b, wdw2, bdw2, wpw2, bpw2,
                                      wlc2, blc2, bufA, bufC);
    k_block<3, 9><<<NBLK, NTH, SMB>>>(bufA, bufC, r3b, wdw3, bdw3, wpw3, bpw3,
                                      wlc3, blc3, out, nullptr);
}

// round 7
// speedup vs baseline: 1.4372x; 1.4372x over previous
#include <cuda_runtime.h>
#include <cuda_fp16.h>

#define LFRAMES 120000
#define C       256
#define TL      64
#define NBLK    1875      // 120000/64 exact
#define NTH     256
#define TSAMP   600000
#define TLF     64

#define HPAD 132          // u32 row stride of A images (k2-dim 128 + 4)
#define BPAD 264          // u32 row stride of B images (n-dim 256 + 8)
#define BMATS 33792       // 128 * BPAD u32 per matrix-half image

typedef unsigned int u32;

__device__ float g_bufA[LFRAMES * C];
__device__ float g_bufB[LFRAMES * C];
__device__ float g_bufC[LFRAMES * C];
__device__ float g_bufD[LFRAMES * C];
// 6 matrices x {hi,lo}: packed f16x2 images [k2][n], row stride BPAD
__device__ __align__(16) u32 g_Bimg[12 * BMATS];

__device__ __forceinline__ float leakyf(float x) { return x >= 0.0f ? x : 0.3f * x; }
__device__ __forceinline__ float quant_div(float x, float s, float o) {
    float q = rintf(x / s - o);
    return fminf(fmaxf(q, -128.0f), 127.0f);
}
__device__ __forceinline__ float quant_mul(float x, float is, float o) {
    float q = rintf(x * is - o);
    return fminf(fmaxf(q, -128.0f), 127.0f);
}
// split (a,b) -> hi f16x2 (a in low half) + lo residual f16x2
__device__ __forceinline__ void split2(float a, float b, u32& hi, u32& lo) {
    __half ha = __float2half_rn(a), hb = __float2half_rn(b);
    __half2 h2 = __halves2half2(ha, hb);
    hi = *reinterpret_cast<u32*>(&h2);
    __half2 l2 = __floats2half2_rn(a - __half2float(ha), b - __half2float(hb));
    lo = *reinterpret_cast<u32*>(&l2);
}
__device__ __forceinline__ void mma16816(float* d, const u32* a, u32 b0, u32 b1) {
    asm volatile("mma.sync.aligned.m16n8k16.row.col.f32.f16.f16.f32 "
                 "{%0,%1,%2,%3}, {%4,%5,%6,%7}, {%8,%9}, {%0,%1,%2,%3};"
                 : "+f"(d[0]), "+f"(d[1]), "+f"(d[2]), "+f"(d[3])
                 : "r"(a[0]), "r"(a[1]), "r"(a[2]), "r"(a[3]), "r"(b0), "r"(b1));
}

// -------------------------------------------------------------------------
// Prep: pack + split weights. img[k2][n] = f16x2{W[2k2][n], W[2k2+1][n]}
// where W[k][n] = w[k*256 + n]. hi image then lo (residual) image.
// -------------------------------------------------------------------------
__global__ void k_prep(const float* __restrict__ w0, const float* __restrict__ w1,
                       const float* __restrict__ w2, const float* __restrict__ w3,
                       const float* __restrict__ w4, const float* __restrict__ w5)
{
    const float* Ws[6] = {w0, w1, w2, w3, w4, w5};
    const int m = blockIdx.y;
    const int idx = blockIdx.x * 256 + threadIdx.x;   // 0..32767
    const int k2 = idx >> 8, n = idx & 255;
    float v0 = Ws[m][(2 * k2) * C + n];
    float v1 = Ws[m][(2 * k2 + 1) * C + n];
    u32 hi, lo;
    split2(v0, v1, hi, lo);
    g_Bimg[(size_t)(2 * m) * BMATS + k2 * BPAD + n]     = hi;
    g_Bimg[(size_t)(2 * m + 1) * BMATS + k2 * BPAD + n] = lo;
}

// -------------------------------------------------------------------------
// First conv (k=10, stride=5, 1->256) + bias; emits res + ci1 = leaky(res)
// -------------------------------------------------------------------------
__global__ __launch_bounds__(NTH) void k_first(
    const float* __restrict__ x, const float* __restrict__ fb,
    const float* __restrict__ wf, const float* __restrict__ bf,
    float* __restrict__ res, float* __restrict__ ci)
{
    __shared__ float sx[5 * TLF + 10];
    const int l0  = blockIdx.x * TLF;
    const int tid = threadIdx.x;
    const int base = 5 * l0;
    for (int i = tid; i < 5 * TLF + 10; i += NTH) {
        int t = base + i;
        float v;
        if (t < 5)              v = fb[t];
        else if (t - 5 < TSAMP) v = x[t - 5];
        else                    v = 0.0f;
        sx[i] = v;
    }
    float w[10];
#pragma unroll
    for (int k = 0; k < 10; k++) w[k] = wf[k * C + tid];
    const float b = bf[tid];
    __syncthreads();
    for (int f = 0; f < TLF; f++) {
        float acc = b;
#pragma unroll
        for (int k = 0; k < 10; k++) acc = fmaf(sx[5 * f + k], w[k], acc);
        res[(l0 + f) * C + tid] = acc;
        ci[(l0 + f) * C + tid]  = leakyf(acc);
    }
}

// -------------------------------------------------------------------------
// Tensor-core GEMM: acc[2][8][4] += A(sH hi/lo) @ B(img hi/lo), K=256.
// A: smem images [64][HPAD] u32 (f16x2 k-pairs). B: streamed K=64 chunks.
// 3-product f16 split: Ah*Bh + Al*Bh + Ah*Bl.
// -------------------------------------------------------------------------
__device__ __forceinline__ void gemmTC(
    float acc[2][8][4],
    const u32* __restrict__ sHhi, const u32* __restrict__ sHlo,
    u32* __restrict__ sBhi, u32* __restrict__ sBlo,
    const u32* __restrict__ imgHi, const u32* __restrict__ imgLo,
    int tid, int mw, int nw, int g, int q)
{
    for (int c = 0; c < 4; c++) {
        __syncthreads();   // previous chunk consumers done
        {
            const float4* s0 = (const float4*)(imgHi + (size_t)c * 32 * BPAD);
            const float4* s1 = (const float4*)(imgLo + (size_t)c * 32 * BPAD);
            float4* d0 = (float4*)sBhi;
            float4* d1 = (float4*)sBlo;
            for (int i = tid; i < 32 * BPAD / 4; i += NTH) {
                d0[i] = s0[i];
                d1[i] = s1[i];
            }
        }
        __syncthreads();

#pragma unroll
        for (int sp = 0; sp < 4; sp++) {
            const int s = c * 4 + sp;          // global kstep
            u32 ah[2][4], al[2][4];
#pragma unroll
            for (int mt = 0; mt < 2; mt++) {
                const int r0 = mw + mt * 16 + g;
                const int k2 = s * 8 + q;
                ah[mt][0] = sHhi[r0 * HPAD + k2];
                ah[mt][1] = sHhi[(r0 + 8) * HPAD + k2];
                ah[mt][2] = sHhi[r0 * HPAD + k2 + 4];
                ah[mt][3] = sHhi[(r0 + 8) * HPAD + k2 + 4];
                al[mt][0] = sHlo[r0 * HPAD + k2];
                al[mt][1] = sHlo[(r0 + 8) * HPAD + k2];
                al[mt][2] = sHlo[r0 * HPAD + k2 + 4];
                al[mt][3] = sHlo[(r0 + 8) * HPAD + k2 + 4];
            }
#pragma unroll
            for (int nb = 0; nb < 8; nb++) {
                const int n = nw + nb * 8 + g;
                const int rb = sp * 8 + q;
                u32 bh0 = sBhi[rb * BPAD + n];
                u32 bh1 = sBhi[(rb + 4) * BPAD + n];
                u32 bl0 = sBlo[rb * BPAD + n];
                u32 bl1 = sBlo[(rb + 4) * BPAD + n];
#pragma unroll
                for (int mt = 0; mt < 2; mt++) {
                    mma16816(acc[mt][nb], ah[mt], bh0, bh1);
                    mma16816(acc[mt][nb], al[mt], bh0, bh1);
                    mma16816(acc[mt][nb], ah[mt], bl0, bl1);
                }
            }
        }
    }
}

// -------------------------------------------------------------------------
// Fused residual block (HMMA version). 64 rows x 256 ch per CTA.
// -------------------------------------------------------------------------
template <int MODE, int DIL>
__global__ __launch_bounds__(NTH) void k_block(
    const float* __restrict__ src,  const float* __restrict__ ciG,
    const float* __restrict__ cbuf,
    const float* __restrict__ wdw,  const float* __restrict__ bdw,
    const float* __restrict__ bpw,  const float* __restrict__ blc,
    const u32* __restrict__ imgs,   // 4 half-images: pwHi, pwLo, lcHi, lcLo
    float* __restrict__ dst,        float* __restrict__ ciOut)
{
    constexpr int PAD = 2 * DIL;
    constexpr float S2 = 5.548006534576416f;
    constexpr float S3 = 4.458680152893066f;
    constexpr float INV_Q1  = (float)(1.0 / 17.62967872619629);
    constexpr float INV_RQ1 = (float)(1.0 / 12.716455459594727);
    constexpr float INV_S3  = (float)(1.0 / 4.458680152893066);

    extern __shared__ u32 smu[];
    u32* sHhi = smu;                     // 64*HPAD
    u32* sHlo = smu + 64 * HPAD;
    u32* sBhi = smu + 2 * 64 * HPAD;     // 32*BPAD
    u32* sBlo = sBhi + 32 * BPAD;
    float* sLUT = (float*)(sBhi);        // LUT lives in B area pre-GEMM? No:
                                         // B area is overwritten; rebuild LUT later.
    const int tid  = threadIdx.x;
    const int w    = tid >> 5;
    const int lane = tid & 31;
    const int q    = lane & 3;
    const int g    = lane >> 2;
    const int mw   = (w & 1) * 32;
    const int nw   = (w >> 1) * 64;
    const int l0   = blockIdx.x * TL;

    // ---- depthwise (k=3, dil=DIL) from global ci stream -> sH images
    {
        const int cp = tid & 127;       // channel pair index (= k2)
        const int c0 = cp * 2;
        const int mb = tid >> 7;        // 0 or 1
        const float2 wd0 = *(const float2*)(wdw + c0);
        const float2 wd1 = *(const float2*)(wdw + C + c0);
        const float2 wd2 = *(const float2*)(wdw + 2 * C + c0);
        const float2 bb  = *(const float2*)(bdw + c0);
#pragma unroll 4
        for (int j = 0; j < 32; j++) {
            const int m = mb + j * 2;
            const int t0 = l0 + m - 2 * DIL;
            const int t1 = l0 + m - DIL;
            float2 x0, x1, x2;
            if (t0 >= 0) x0 = *(const float2*)(ciG + (size_t)t0 * C + c0);
            else {
                float2 bv = *(const float2*)(cbuf + (t0 + PAD) * C + c0);
                if (MODE == 1) x0 = bv;
                else if (MODE == 2) { x0.x = quant_div(bv.x, S2, 47.0f); x0.y = quant_div(bv.y, S2, 47.0f); }
                else { x0.x = quant_div(bv.x, S3, 38.0f); x0.y = quant_div(bv.y, S3, 38.0f); }
            }
            if (t1 >= 0) x1 = *(const float2*)(ciG + (size_t)t1 * C + c0);
            else {
                float2 bv = *(const float2*)(cbuf + (t1 + PAD) * C + c0);
                if (MODE == 1) x1 = bv;
                else if (MODE == 2) { x1.x = quant_div(bv.x, S2, 47.0f); x1.y = quant_div(bv.y, S2, 47.0f); }
                else { x1.x = quant_div(bv.x, S3, 38.0f); x1.y = quant_div(bv.y, S3, 38.0f); }
            }
            x2 = *(const float2*)(ciG + (size_t)(l0 + m) * C + c0);
            float h0 = bb.x, h1 = bb.y;
            h0 = fmaf(x0.x, wd0.x, h0); h1 = fmaf(x0.y, wd0.y, h1);
            h0 = fmaf(x1.x, wd1.x, h0); h1 = fmaf(x1.y, wd1.y, h1);
            h0 = fmaf(x2.x, wd2.x, h0); h1 = fmaf(x2.y, wd2.y, h1);
            u32 hi, lo;
            split2(h0, h1, hi, lo);
            sHhi[m * HPAD + cp] = hi;
            sHlo[m * HPAD + cp] = lo;
        }
    }
    // (gemmTC starts with __syncthreads)

    // ---- GEMM1: P = H @ Wpw + bpw
    float acc[2][8][4];
#pragma unroll
    for (int nb = 0; nb < 8; nb++) {
        const int cn = nw + nb * 8 + q * 2;
        float b0 = bpw[cn], b1 = bpw[cn + 1];
#pragma unroll
        for (int mt = 0; mt < 2; mt++) {
            acc[mt][nb][0] = b0; acc[mt][nb][1] = b1;
            acc[mt][nb][2] = b0; acc[mt][nb][3] = b1;
        }
    }
    gemmTC(acc, sHhi, sHlo, sBhi, sBlo, imgs, imgs + BMATS, tid, mw, nw, g, q);
    __syncthreads();   // all A-fragment reads of sH done

    // ---- epilogue1: quant/leaky, split, write back into sH images
#pragma unroll
    for (int mt = 0; mt < 2; mt++) {
        const int r0 = mw + mt * 16 + g;
#pragma unroll
        for (int nb = 0; nb < 8; nb++) {
            const int k2p = nw / 2 + nb * 4 + q;   // (nw+nb*8+2q)/2
            float p0 = acc[mt][nb][0], p1 = acc[mt][nb][1];
            float p2 = acc[mt][nb][2], p3 = acc[mt][nb][3];
            if (MODE == 1) {
                p0 = quant_mul(p0, INV_Q1, -67.0f);
                p1 = quant_mul(p1, INV_Q1, -67.0f);
                p2 = quant_mul(p2, INV_Q1, -67.0f);
                p3 = quant_mul(p3, INV_Q1, -67.0f);
            }
            p0 = leakyf(p0); p1 = leakyf(p1); p2 = leakyf(p2); p3 = leakyf(p3);
            u32 hi, lo;
            split2(p0, p1, hi, lo);
            sHhi[r0 * HPAD + k2p] = hi;
            sHlo[r0 * HPAD + k2p] = lo;
            split2(p2, p3, hi, lo);
            sHhi[(r0 + 8) * HPAD + k2p] = hi;
            sHlo[(r0 + 8) * HPAD + k2p] = lo;
        }
    }

    // ---- GEMM2: O = P @ Wlc + blc
#pragma unroll
    for (int nb = 0; nb < 8; nb++) {
        const int cn = nw + nb * 8 + q * 2;
        float b0 = blc[cn], b1 = blc[cn + 1];
#pragma unroll
        for (int mt = 0; mt < 2; mt++) {
            acc[mt][nb][0] = b0; acc[mt][nb][1] = b1;
            acc[mt][nb][2] = b0; acc[mt][nb][3] = b1;
        }
    }
    gemmTC(acc, sHhi, sHlo, sBhi, sBlo, imgs + 2 * BMATS, imgs + 3 * BMATS,
           tid, mw, nw, g, q);

    // ---- LUT for MODE1 ci emission (exact quant of int lattice)
    if (MODE == 1) {
        __syncthreads();                 // B area free (GEMM2 compute done)
        sLUT = (float*)sBhi;
        sLUT[tid] = quant_div((leakyf((float)(tid - 128)) + 47.0f) * S2, S2, 47.0f);
        __syncthreads();
    }

    // ---- final epilogue: residual + mode outputs (+ next ci stream)
#pragma unroll
    for (int mt = 0; mt < 2; mt++) {
#pragma unroll
        for (int nb = 0; nb < 8; nb++) {
            const int cn = nw + nb * 8 + q * 2;
#pragma unroll
            for (int half = 0; half < 2; half++) {
                const int l = l0 + mw + mt * 16 + g + half * 8;
                float o0 = acc[mt][nb][half * 2];
                float o1 = acc[mt][nb][half * 2 + 1];
                float2 r = *(const float2*)(src + (size_t)l * C + cn);
                float2 val, civ;
                if (MODE == 1) {
                    val.x = quant_mul(r.x + (o0 - 16.0f) * 6.528060436248779f, INV_RQ1, -23.0f);
                    val.y = quant_mul(r.y + (o1 - 16.0f) * 6.528060436248779f, INV_RQ1, -23.0f);
                    civ.x = sLUT[(int)val.x + 128];
                    civ.y = sLUT[(int)val.y + 128];
                } else if (MODE == 2) {
                    val.x = o0 + r.x;
                    val.y = o1 + r.y;
                    civ.x = quant_mul((leakyf(val.x) + 38.0f) * S3, INV_S3, 38.0f);
                    civ.y = quant_mul((leakyf(val.y) + 38.0f) * S3, INV_S3, 38.0f);
                } else {
                    val.x = (leakyf(o0 + r.x) + 34.0f) * 3.698859930038452f;
                    val.y = (leakyf(o1 + r.y) + 34.0f) * 3.698859930038452f;
                }
                *(float2*)(dst + (size_t)l * C + cn) = val;
                if (MODE != 3) *(float2*)(ciOut + (size_t)l * C + cn) = civ;
            }
        }
    }
}

// -------------------------------------------------------------------------
extern "C" void kernel_launch(void* const* d_in, const int* in_sizes, int n_in,
                              void* d_out, int out_size)
{
    (void)in_sizes; (void)n_in; (void)out_size;
    const float* x    = (const float*)d_in[0];
    const float* fb   = (const float*)d_in[1];
    const float* r1b  = (const float*)d_in[2];
    const float* r2b  = (const float*)d_in[3];
    const float* r3b  = (const float*)d_in[4];
    const float* wf   = (const float*)d_in[5];
    const float* bf   = (const float*)d_in[6];
    const float* wdw1 = (const float*)d_in[7],  *bdw1 = (const float*)d_in[8];
    const float* wpw1 = (const float*)d_in[9],  *bpw1 = (const float*)d_in[10];
    const float* wlc1 = (const float*)d_in[11], *blc1 = (const float*)d_in[12];
    const float* wdw2 = (const float*)d_in[13], *bdw2 = (const float*)d_in[14];
    const float* wpw2 = (const float*)d_in[15], *bpw2 = (const float*)d_in[16];
    const float* wlc2 = (const float*)d_in[17], *blc2 = (const float*)d_in[18];
    const float* wdw3 = (const float*)d_in[19], *bdw3 = (const float*)d_in[20];
    const float* wpw3 = (const float*)d_in[21], *bpw3 = (const float*)d_in[22];
    const float* wlc3 = (const float*)d_in[23], *blc3 = (const float*)d_in[24];
    float* out = (float*)d_out;

    float *bufA, *bufB, *bufC, *bufD;
    u32* img;
    cudaGetSymbolAddress((void**)&bufA, g_bufA);
    cudaGetSymbolAddress((void**)&bufB, g_bufB);
    cudaGetSymbolAddress((void**)&bufC, g_bufC);
    cudaGetSymbolAddress((void**)&bufD, g_bufD);
    cudaGetSymbolAddress((void**)&img,  g_Bimg);

    const int SMB = (2 * 64 * HPAD + 2 * 32 * BPAD) * 4;  // 135,168 B
    cudaFuncSetAttribute(k_block<1, 1>, cudaFuncAttributeMaxDynamicSharedMemorySize, SMB);
    cudaFuncSetAttribute(k_block<2, 3>, cudaFuncAttributeMaxDynamicSharedMemorySize, SMB);
    cudaFuncSetAttribute(k_block<3, 9>, cudaFuncAttributeMaxDynamicSharedMemorySize, SMB);

    k_prep<<<dim3(128, 6), 256>>>(wpw1, wlc1, wpw2, wlc2, wpw3, wlc3);
    k_first<<<LFRAMES / TLF, NTH>>>(x, fb, wf, bf, bufA, bufC);
    k_block<1, 1><<<NBLK, NTH, SMB>>>(bufA, bufC, r1b, wdw1, bdw1, bpw1, blc1,
                                      img + 0 * BMATS, bufB, bufD);
    k_block<2, 3><<<NBLK, NTH, SMB>>>(bufB, bufD, r2b, wdw2, bdw2, bpw2, blc2,
                                      img + 4 * BMATS, bufA, bufC);
    k_block<3, 9><<<NBLK, NTH, SMB>>>(bufA, bufC, r3b, wdw3, bdw3, bpw3, blc3,
                                      img + 8 * BMATS, out, nullptr);
}